// round 17
// baseline (speedup 1.0000x reference)
#include <cuda_runtime.h>
#include <cuda_bf16.h>
#include <cuda_fp8.h>
#include <cstdint>

#define B_  64
#define C_  256
#define Wn_ 256
#define E_  2048
#define D_  2048

#define KT8    128           // fp8 K per stage (128B rows)
#define KS8    (E_/KT8)      // 16 k-steps per n-chunk (fp8 main GEMM)
#define NCHP   8             // n-chunks (of 128 cols) per CTA; 2 CTAs cover D
#define KQ_    8             // small-GEMM K-splits
#define KSL    (E_/KQ_/64)   // 4 k-steps per small-GEMM CTA (KT=64 bf16)

// ---------------- scratch ----------------
__device__ int   g_idx[B_];
__device__ float g_leader[B_*D_];
__device__ float g_leadp[KQ_][B_*D_];
__device__ float g_up[KQ_*B_*E_];
__device__ float g_u[B_*E_];
__device__ float g_dot[B_*Wn_];
__device__ float g_nrmp[2][B_*Wn_];
__device__ __nv_bfloat16 g_xt16[(size_t)B_*Wn_*E_];   // 64 MB (for dot pass)
__device__ uint8_t       g_xtq[(size_t)B_*Wn_*E_];    // 32 MB e4m3
__device__ uint8_t       g_wq[(size_t)D_*E_];         //  4 MB e4m3 (W*64)
__device__ __nv_bfloat16 g_wi16[(size_t)D_*E_];       //  8 MB
__device__ __nv_bfloat16 g_wt16[(size_t)E_*D_];       //  8 MB  W_words^T
__device__ __nv_bfloat16 g_xl16[(size_t)B_*E_];       // leader inputs
__device__ __nv_bfloat16 g_lead16[(size_t)B_*D_];     // leader bf16

// ---------------- helpers ----------------
__device__ __forceinline__ uint32_t swz(uint32_t o){ return o ^ ((o>>3)&0x70); }

__device__ __forceinline__ void cpasync16(uint32_t s, const void* g){
  asm volatile("cp.async.cg.shared.global [%0],[%1],16;"::"r"(s),"l"(g));
}
__device__ __forceinline__ void cpcommit(){ asm volatile("cp.async.commit_group;"); }
__device__ __forceinline__ void cpwait0(){ asm volatile("cp.async.wait_group 0;"); }

__device__ __forceinline__ void cp_mbar_arrive(uint32_t mb){
  asm volatile("cp.async.mbarrier.arrive.noinc.shared.b64 [%0];" :: "r"(mb) : "memory");
}
__device__ __forceinline__ void mbar_arrive(uint32_t mb){
  asm volatile("mbarrier.arrive.shared.b64 _, [%0];" :: "r"(mb) : "memory");
}
__device__ __forceinline__ void mbar_init(uint32_t mb, uint32_t cnt){
  asm volatile("mbarrier.init.shared.b64 [%0], %1;" :: "r"(mb), "r"(cnt) : "memory");
}
__device__ __forceinline__ void mbar_wait(uint32_t mb, uint32_t parity){
  uint32_t done;
  asm volatile(
    "{\n\t.reg .pred p;\n\t"
    "mbarrier.try_wait.parity.acquire.cta.shared::cta.b64 p, [%1], %2;\n\t"
    "selp.b32 %0, 1, 0, p;\n\t}"
    : "=r"(done) : "r"(mb), "r"(parity) : "memory");
  if (!done){
    asm volatile(
      "{\n\t.reg .pred P1;\n\t"
      "WL_%=:\n\t"
      "mbarrier.try_wait.parity.acquire.cta.shared::cta.b64 P1, [%0], %1, 0x989680;\n\t"
      "@P1 bra.uni WD_%=;\n\t"
      "bra.uni WL_%=;\n\t"
      "WD_%=:\n\t}"
      :: "r"(mb), "r"(parity) : "memory");
  }
}

__device__ __forceinline__ void ldsm4(uint32_t* r, uint32_t a){
  asm volatile("ldmatrix.sync.aligned.m8n8.x4.shared.b16 {%0,%1,%2,%3},[%4];"
   :"=r"(r[0]),"=r"(r[1]),"=r"(r[2]),"=r"(r[3]):"r"(a));
}
__device__ __forceinline__ void mma16816(float* c, const uint32_t* a, const uint32_t* b){
  asm volatile("mma.sync.aligned.m16n8k16.row.col.f32.bf16.bf16.f32 "
   "{%0,%1,%2,%3},{%4,%5,%6,%7},{%8,%9},{%0,%1,%2,%3};"
   :"+f"(c[0]),"+f"(c[1]),"+f"(c[2]),"+f"(c[3])
   :"r"(a[0]),"r"(a[1]),"r"(a[2]),"r"(a[3]),"r"(b[0]),"r"(b[1]));
}
__device__ __forceinline__ void mma16832f8(float* c, const uint32_t* a, const uint32_t* b){
  asm volatile("mma.sync.aligned.m16n8k32.row.col.f32.e4m3.e4m3.f32 "
   "{%0,%1,%2,%3},{%4,%5,%6,%7},{%8,%9},{%0,%1,%2,%3};"
   :"+f"(c[0]),"+f"(c[1]),"+f"(c[2]),"+f"(c[3])
   :"r"(a[0]),"r"(a[1]),"r"(a[2]),"r"(a[3]),"r"(b[0]),"r"(b[1]));
}

__device__ __forceinline__ uint32_t f4_to_e4m3(float4 v, float sc){
  __nv_fp8x2_storage_t lo = __nv_cvt_float2_to_fp8x2(make_float2(v.x*sc, v.y*sc),
                                                     __NV_SATFINITE, __NV_E4M3);
  __nv_fp8x2_storage_t hi = __nv_cvt_float2_to_fp8x2(make_float2(v.z*sc, v.w*sc),
                                                     __NV_SATFINITE, __NV_E4M3);
  return (uint32_t)lo | ((uint32_t)hi << 16);
}

// ---------------- kernel 1: argmax + gather leader row -> bf16 ----------------
__global__ void k_argmax_gather(const float* __restrict__ y,
                                const float* __restrict__ x_img){
  int b = blockIdx.x, t = threadIdx.x;
  __shared__ float vs[256]; __shared__ int is[256];
  vs[t] = y[b*C_ + t]; is[t] = t; __syncthreads();
  for (int s=128; s>0; s>>=1){
    if (t < s){
      float v2 = vs[t+s]; int i2 = is[t+s];
      if (v2 > vs[t] || (v2 == vs[t] && i2 < is[t])) { vs[t]=v2; is[t]=i2; }
    }
    __syncthreads();
  }
  if (t==0) g_idx[b] = is[0];
  __syncthreads();
  int idx = is[0];
  const float4* src = (const float4*)(x_img + ((size_t)b*C_ + idx)*E_);
  __nv_bfloat162* dst = (__nv_bfloat162*)(g_xl16 + (size_t)b*E_);
  for (int i=t; i<E_/4; i+=256){
    float4 v = src[i];
    dst[i*2+0] = __floats2bfloat162_rn(v.x, v.y);
    dst[i*2+1] = __floats2bfloat162_rn(v.z, v.w);
  }
}

// ---------------- kernel 2: fp32 -> bf16/e4m3 bulk convert ----------------
// x_txt -> g_xt16 (bf16) + g_xtq (e4m3); Ww -> g_wq (e4m3 * 64); Wi -> g_wi16 (bf16)
__global__ void k_convert(const float* __restrict__ xt, const float* __restrict__ Ww,
                          const float* __restrict__ Wi){
  const long NX4  = (long)B_*Wn_*E_/4;
  const long NW4  = (long)D_*E_/4;
  long i = (long)blockIdx.x*blockDim.x + threadIdx.x;
  long stride = (long)gridDim.x*blockDim.x;
  for (; i < NX4 + 2*NW4; i += stride){
    if (i < NX4){
      float4 v = ((const float4*)xt)[i];
      __nv_bfloat162* d2 = (__nv_bfloat162*)(g_xt16 + i*4);
      d2[0] = __floats2bfloat162_rn(v.x, v.y);
      d2[1] = __floats2bfloat162_rn(v.z, v.w);
      ((uint32_t*)g_xtq)[i] = f4_to_e4m3(v, 1.0f);
    } else if (i < NX4+NW4){
      long j = i - NX4;
      float4 v = ((const float4*)Ww)[j];
      ((uint32_t*)g_wq)[j] = f4_to_e4m3(v, 64.0f);
    } else {
      long j = i - NX4 - NW4;
      float4 v = ((const float4*)Wi)[j];
      __nv_bfloat162* d2 = (__nv_bfloat162*)(g_wi16 + j*4);
      d2[0] = __floats2bfloat162_rn(v.x, v.y);
      d2[1] = __floats2bfloat162_rn(v.z, v.w);
    }
  }
}

// ---------------- kernel 3: transpose W_words -> bf16 W^T [E, D] ----------------
__global__ void k_wt(const float* __restrict__ Ww){
  __shared__ float tile[32][33];
  int e0 = blockIdx.x*32, d0 = blockIdx.y*32;
  int c = threadIdx.x, r0 = threadIdx.y;          // 32 x 8
  #pragma unroll
  for (int rr=r0; rr<32; rr+=8) tile[rr][c] = Ww[(size_t)(d0+rr)*E_ + e0 + c];
  __syncthreads();
  #pragma unroll
  for (int rr=r0; rr<32; rr+=8)
    g_wt16[(size_t)(e0+rr)*D_ + d0 + c] = __float2bfloat16(tile[c][rr]);
}

// ---------------- kernel 4: generic small GEMM M=64, split-K (bf16 mma.sync) ----
// which=0: leader partials = xl16 @ wi16^T ; which=1: u partials = lead16 @ wt16^T
// grid (16, 8) = (n-tile of 128, k-eighth). K=256 per CTA.
__global__ void __launch_bounds__(256) k_gemm64(int which){
  __shared__ __align__(1024) char sm[49152];
  const int t = threadIdx.x, dt = blockIdx.x, kq = blockIdx.y;
  const int w = t>>5, l = t&31;
  const int wm = w>>2, wn = w&3;
  uint32_t sb = (uint32_t)__cvta_generic_to_shared(sm);

  const __nv_bfloat16* A0 = which ? g_lead16 : g_xl16;
  const __nv_bfloat16* B0 = which ? g_wt16   : g_wi16;
  float* out0 = which ? g_up : &g_leadp[0][0];

  const __nv_bfloat16* Abase = A0 + (size_t)kq*(E_/KQ_);
  const __nv_bfloat16* Bbase = B0 + (size_t)dt*128*E_ + (size_t)kq*(E_/KQ_);

  float c[2][4][4];
  #pragma unroll
  for (int i=0;i<2;i++) for (int j=0;j<4;j++) for (int e=0;e<4;e++) c[i][j][e]=0.f;

  {
    int u = t; int row=u>>3, seg=u&7;
    cpasync16(sb + 0 + swz(row*128+seg*16), Abase + (size_t)row*E_ + seg*8);
    u = t+256; row=u>>3; seg=u&7;
    cpasync16(sb + 0 + swz(row*128+seg*16), Abase + (size_t)row*E_ + seg*8);
    #pragma unroll
    for (int i=0;i<4;i++){ int v = t+256*i; int r2=v>>3, s2=v&7;
      cpasync16(sb + 16384 + swz(r2*128+s2*16), Bbase + (size_t)r2*E_ + s2*8); }
    cpcommit();
  }
  const uint32_t aRow = (uint32_t)(32*wm + (l&15));
  const uint32_t aSeg = (uint32_t)((l>>4)&1);
  const uint32_t bR4  = (uint32_t)(32*wn + (l&7) + 8*((l>>4)&1));
  const uint32_t bS4  = (uint32_t)((l>>3)&1);

  for (int ks=0; ks<KSL; ks++){
    cpwait0(); __syncthreads();
    if (ks+1 < KSL){
      int p = (ks+1)&1;
      int u=t, row=u>>3, seg=u&7;
      cpasync16(sb + p*8192 + swz(row*128+seg*16), Abase + (size_t)row*E_ + (size_t)(ks+1)*64 + seg*8);
      u=t+256; row=u>>3; seg=u&7;
      cpasync16(sb + p*8192 + swz(row*128+seg*16), Abase + (size_t)row*E_ + (size_t)(ks+1)*64 + seg*8);
      #pragma unroll
      for (int i=0;i<4;i++){ int v=t+256*i; int r2=v>>3, s2=v&7;
        cpasync16(sb + 16384 + p*16384 + swz(r2*128+s2*16),
                  Bbase + (size_t)r2*E_ + (size_t)(ks+1)*64 + s2*8); }
      cpcommit();
    }
    uint32_t ab = sb + (ks&1)*8192;
    uint32_t bb = sb + 16384 + (ks&1)*16384;
    #pragma unroll
    for (int kk=0; kk<4; kk++){
      uint32_t a[2][4], bf4[2][4];
      #pragma unroll
      for (int im=0;im<2;im++)
        ldsm4(a[im], ab + swz((aRow + 16*im)*128 + (kk*16 + aSeg*8)*2));
      #pragma unroll
      for (int pr=0;pr<2;pr++)
        ldsm4(bf4[pr], bb + swz((bR4 + 16*pr)*128 + (kk*16 + bS4*8)*2));
      #pragma unroll
      for (int im=0;im<2;im++)
        #pragma unroll
        for (int pr=0;pr<2;pr++){
          mma16816(c[im][2*pr],   a[im], &bf4[pr][0]);
          mma16816(c[im][2*pr+1], a[im], &bf4[pr][2]);
        }
    }
    __syncthreads();
  }
  float* outp = out0 + (size_t)kq*(B_*D_);
  #pragma unroll
  for (int im=0;im<2;im++)
    #pragma unroll
    for (int in_=0;in_<4;in_++)
      #pragma unroll
      for (int e=0;e<4;e++){
        int row = 32*wm + 16*im + (l>>2) + 8*(e>>1);
        int col = 32*wn + 8*in_ + 2*(l&3) + (e&1);
        outp[(size_t)row*D_ + dt*128 + col] = c[im][in_][e];
      }
}

// ---------------- kernel 4b: merge leader partials + bias (fp32 + bf16) --------
__global__ void k_leadmerge(const float* __restrict__ bimg){
  int b = blockIdx.x, q4 = blockIdx.y, t = threadIdx.x;
  int d = q4*512 + t;
  #pragma unroll
  for (int it=0; it<2; it++, d+=256){
    int o = b*D_ + d;
    float s = bimg[d];
    #pragma unroll
    for (int q=0;q<KQ_;q++) s += g_leadp[q][o];
    g_leader[o] = s;
    g_lead16[o] = __float2bfloat16(s);
  }
}

// ---------------- kernel 4c: merge u partials ----------------------------------
__global__ void k_umerge(){
  int b = blockIdx.x, q4 = blockIdx.y, t = threadIdx.x;
  int e = q4*512 + t;
  #pragma unroll
  for (int it=0; it<2; it++, e+=256){
    int o = b*E_ + e;
    float s = 0.f;
    #pragma unroll
    for (int q=0;q<KQ_;q++) s += g_up[(size_t)q*(B_*E_) + o];
    g_u[o] = s;
  }
}

// ---------------- kernel 5: norm GEMM (e4m3 HMMA, mbarrier ring) ---------------
// grid (2, 64, 2) = (wtile, b, d-half). 256 thr, 8 warps as 2(M)x4(N).
// KT8=128 fp8 per 16KB stage; 16 k-steps per n-chunk; consume-first ring of 3.
#define SM_A    0          // 3 x 16384
#define SM_B    49152      // 3 x 16384
#define SM_BIAS 98304      // 128 f
#define SM_RN   98816      // 512 f
#define SM_MBAR 100864     // full[3] @ +0, empty[3] @ +24
#define SMEM_TOTAL 100928

__global__ void __launch_bounds__(256,2) k_main(const float* __restrict__ bwords){
  extern __shared__ __align__(1024) char smem[];
  const int t = threadIdx.x;
  const int wt = blockIdx.x, b = blockIdx.y, dh = blockIdx.z;
  const int w = t>>5, l = t&31;
  const int wm = w>>2, wn = w&3;
  const int gid = l>>2, qid = l&3;
  uint32_t sbase = (uint32_t)__cvta_generic_to_shared(smem);
  float* bias_s = (float*)(smem + SM_BIAS);
  float* red_n  = (float*)(smem + SM_RN);
  const uint32_t mb_full  = sbase + SM_MBAR;
  const uint32_t mb_empty = sbase + SM_MBAR + 24;

  if (t == 0){
    #pragma unroll
    for (int i=0;i<3;i++){ mbar_init(mb_full + i*8, 256); mbar_init(mb_empty + i*8, 8); }
  }
  __syncthreads();

  const uint8_t* Abase  = g_xtq + (size_t)(b*Wn_ + wt*128)*E_;
  const uint8_t* Bbase0 = g_wq  + (size_t)(dh*NCHP)*128*E_;

  // per-thread fixed offsets: 4 chunks of 16B per tile; rows are E_ bytes
  uint32_t aSm[4]; uint32_t gOff[4];
  #pragma unroll
  for (int i=0;i<4;i++){
    int u = t + 256*i; int row = u>>3, seg = u&7;
    aSm[i]  = sbase + SM_A + swz((uint32_t)(row*128 + seg*16));
    gOff[i] = (uint32_t)(row*E_ + seg*16);
  }

  // prologue: produce stages 0,1
  #pragma unroll
  for (int gp=0; gp<2; gp++){
    const uint8_t* Ap = Abase  + gp*KT8;
    const uint8_t* Bp = Bbase0 + gp*KT8;
    #pragma unroll
    for (int i=0;i<4;i++) cpasync16(aSm[i] + (uint32_t)(gp*16384), Ap + gOff[i]);
    #pragma unroll
    for (int i=0;i<4;i++) cpasync16(aSm[i] + (uint32_t)(49152 + gp*16384), Bp + gOff[i]);
    cp_mbar_arrive(mb_full + gp*8);
  }

  const uint32_t aRow = (uint32_t)(64*wm + (l&15));
  const uint32_t aSeg = (uint32_t)((l>>4)&1);
  const uint32_t bR4  = (uint32_t)(32*wn + (l&7) + 8*((l>>4)&1));
  const uint32_t bS4  = (uint32_t)((l>>3)&1);

  float nrm_tot = 0.f;
  float c[4][4][4];

  int sP = 2, pPw = 1;
  int sC = 0, pC = 0;

  for (int nc=0; nc<NCHP; nc++){
    #pragma unroll
    for (int i=0;i<4;i++)
      #pragma unroll
      for (int j=0;j<4;j++)
        #pragma unroll
        for (int e=0;e<4;e++) c[i][j][e]=0.f;

    for (int ks=0; ks<KS8; ks++){
      const int gs = nc*KS8 + ks;
      // ---- consume stage gs first ----
      mbar_wait(mb_full + sC*8, (uint32_t)pC);
      {
        uint32_t abuf = sbase + SM_A + (uint32_t)(sC*16384);
        uint32_t bbuf = sbase + SM_B + (uint32_t)(sC*16384);
        #pragma unroll
        for (int kk=0; kk<4; kk++){
          uint32_t a[4][4], bf4[2][4];
          #pragma unroll
          for (int im=0;im<4;im++)
            ldsm4(a[im], abuf + swz((aRow + 16*im)*128 + kk*32 + aSeg*16));
          #pragma unroll
          for (int pr=0;pr<2;pr++)
            ldsm4(bf4[pr], bbuf + swz((bR4 + 16*pr)*128 + kk*32 + bS4*16));
          #pragma unroll
          for (int im=0;im<4;im++)
            #pragma unroll
            for (int pr=0;pr<2;pr++){
              mma16832f8(c[im][2*pr],   a[im], &bf4[pr][0]);
              mma16832f8(c[im][2*pr+1], a[im], &bf4[pr][2]);
            }
        }
      }
      __syncwarp();
      if (l == 0) mbar_arrive(mb_empty + sC*8);
      if (++sC == 3){ sC = 0; pC ^= 1; }

      // ---- produce stage gs+2 ----
      if (gs+2 < NCHP*KS8){
        mbar_wait(mb_empty + sP*8, (uint32_t)pPw);
        const int gp = gs+2, ksP = gp & (KS8-1), ncP = gp >> 4;
        const uint8_t* Ap = Abase  + ksP*KT8;
        const uint8_t* Bp = Bbase0 + (size_t)(ncP*128)*E_ + ksP*KT8;
        const uint32_t so = (uint32_t)(sP*16384);
        #pragma unroll
        for (int i=0;i<4;i++) cpasync16(aSm[i] + so, Ap + gOff[i]);
        #pragma unroll
        for (int i=0;i<4;i++) cpasync16(aSm[i] + 49152u + so, Bp + gOff[i]);
        cp_mbar_arrive(mb_full + sP*8);
        if (++sP == 3){ sP = 0; pPw ^= 1; }
      }
    }

    // ---- epilogue: fold C into per-row nrm (v = c/64 + bias) ----
    const int ncg = dh*NCHP + nc;
    __syncthreads();
    if (t < 128) bias_s[t] = bwords[ncg*128 + t];
    __syncthreads();
    float np2[8];
    #pragma unroll
    for (int s=0;s<8;s++) np2[s]=0.f;
    #pragma unroll
    for (int im=0;im<4;im++)
      #pragma unroll
      for (int in_=0;in_<4;in_++)
        #pragma unroll
        for (int e=0;e<4;e++){
          int col = 32*wn + 8*in_ + 2*qid + (e&1);
          float v = c[im][in_][e]*0.015625f + bias_s[col];
          np2[im*2 + (e>>1)] += v * v;
        }
    #pragma unroll
    for (int s=0;s<8;s++){
      np2[s] += __shfl_xor_sync(0xffffffffu, np2[s], 1);
      np2[s] += __shfl_xor_sync(0xffffffffu, np2[s], 2);
    }
    if (qid == 0){
      #pragma unroll
      for (int s=0;s<8;s++){
        int r = 64*wm + 16*(s>>1) + gid + 8*(s&1);
        red_n[wn*128 + r] = np2[s];
      }
    }
    __syncthreads();
    if (t < 128){
      float ns=0.f;
      #pragma unroll
      for (int q=0;q<4;q++) ns += red_n[q*128+t];
      nrm_tot += ns;
    }
    __syncthreads();
  }

  if (t < 128){
    int o = b*Wn_ + wt*128 + t;
    g_nrmp[dh][o] = nrm_tot;
  }
}

// ---------------- kernel 6: dot = u.x + leader.bw (exact path) -----------------
__global__ void __launch_bounds__(256) k_dot(const float* __restrict__ bw){
  int b = blockIdx.x, t = threadIdx.x;
  int wp = t>>5, l = t&31;
  __shared__ float sh[256];
  __shared__ float lb_s;
  // lb = leader . bw
  float acc = 0.f;
  const float* lr = g_leader + b*D_;
  for (int i=t; i<D_; i+=256) acc += lr[i]*bw[i];
  sh[t] = acc; __syncthreads();
  for (int st=128; st>0; st>>=1){ if (t<st) sh[t]+=sh[t+st]; __syncthreads(); }
  if (t==0) lb_s = sh[0];
  __syncthreads();
  float lb = lb_s;

  // u[b] into per-lane registers (float2 pairs, lane-strided)
  const float2* u2 = (const float2*)(g_u + (size_t)b*E_);
  float2 ur[32];
  #pragma unroll
  for (int i=0;i<32;i++) ur[i] = u2[l + 32*i];

  // 8 warps x 32 rows
  for (int row = wp; row < Wn_; row += 8){
    const uint32_t* xr = (const uint32_t*)(g_xt16 + ((size_t)(b*Wn_ + row))*E_);
    float s = 0.f;
    #pragma unroll
    for (int i=0;i<32;i++){
      uint32_t p = xr[l + 32*i];
      __nv_bfloat162 x2 = *reinterpret_cast<__nv_bfloat162*>(&p);
      float2 xf = __bfloat1622float2(x2);
      s += xf.x*ur[i].x + xf.y*ur[i].y;
    }
    #pragma unroll
    for (int o=16; o>0; o>>=1) s += __shfl_xor_sync(0xffffffffu, s, o);
    if (l == 0) g_dot[b*Wn_ + row] = s + lb;
  }
}

// ---------------- kernel 7: cosine + softmax ----------------
__global__ void k_final(float* __restrict__ out){
  int b = blockIdx.x, t = threadIdx.x;
  __shared__ float sh[256];
  float s = 0.f;
  const float* lr = g_leader + b*D_;
  for (int i=t; i<D_; i+=256){ float v = lr[i]; s += v*v; }
  sh[t] = s; __syncthreads();
  for (int st=128; st>0; st>>=1){ if (t<st) sh[t]+=sh[t+st]; __syncthreads(); }
  float ln = sqrtf(sh[0]);
  __syncthreads();

  int o = b*Wn_ + t;
  float dot = g_dot[o];
  float nr  = sqrtf(g_nrmp[0][o] + g_nrmp[1][o]);
  float logit = dot / fmaxf(ln*nr, 1e-8f);

  sh[t] = logit; __syncthreads();
  for (int st=128; st>0; st>>=1){ if (t<st) sh[t]=fmaxf(sh[t],sh[t+st]); __syncthreads(); }
  float mx = sh[0]; __syncthreads();
  float ex = expf(logit - mx);
  sh[t] = ex; __syncthreads();
  for (int st=128; st>0; st>>=1){ if (t<st) sh[t]+=sh[t+st]; __syncthreads(); }
  out[b*Wn_ + t] = ex / sh[0];
}

// ---------------- launcher ----------------
extern "C" void kernel_launch(void* const* d_in, const int* in_sizes, int n_in,
                              void* d_out, int out_size){
  const float* x_img = (const float*)d_in[0];
  const float* x_txt = (const float*)d_in[1];
  const float* y     = (const float*)d_in[2];
  const float* Wimg  = (const float*)d_in[3];
  const float* bimg  = (const float*)d_in[4];
  const float* Ww    = (const float*)d_in[5];
  const float* bw    = (const float*)d_in[6];
  float* out = (float*)d_out;

  cudaFuncSetAttribute(k_main, cudaFuncAttributeMaxDynamicSharedMemorySize, SMEM_TOTAL);

  k_argmax_gather<<<B_, 256>>>(y, x_img);
  k_convert<<<2048, 256>>>(x_txt, Ww, Wimg);
  k_wt<<<dim3(E_/32, D_/32), dim3(32, 8)>>>(Ww);
  k_gemm64<<<dim3(D_/128, KQ_), 256>>>(0);          // leader partials
  k_leadmerge<<<dim3(B_, 4), 256>>>(bimg);
  k_gemm64<<<dim3(E_/128, KQ_), 256>>>(1);          // u partials
  k_umerge<<<dim3(B_, 4), 256>>>();
  k_main<<<dim3(2, B_, 2), 256, SMEM_TOTAL>>>(bw);  // fp8 norm GEMM
  k_dot<<<B_, 256>>>(bw);
  k_final<<<B_, 256>>>(out);
}